// round 4
// baseline (speedup 1.0000x reference)
#include <cuda_runtime.h>
#include <cstdint>

#define N_ROWS 8192
#define F_COLS 8192
#define K_SEL  2867u
#define WORDS_PER_ROW 256   /* 8192 / 32 */

// Scratch (static __device__ arrays — allocation-free per harness rules)
__device__ __align__(16) float g_boost[F_COLS];
// Transposed mask: g_mask[wordcol * N_ROWS + row]
__device__ unsigned g_mask[WORDS_PER_ROW * N_ROWS];

// ---------------------------------------------------------------------------
// Kernel 1: boost = exp(BETA*(target - duty_cycle))
// ---------------------------------------------------------------------------
__global__ void boost_kernel(const float* __restrict__ dc) {
    int j = blockIdx.x * blockDim.x + threadIdx.x;
    if (j < F_COLS) {
        const float target = 2867.0f / 8192.0f;   // exact dyadic
        g_boost[j] = expf(1.5f * (target - dc[j]));
    }
}

// ---------------------------------------------------------------------------
// Radix-select over a 2048-bin histogram: find bin B with
//   count(bins > B) < kr <= count(bins >= B);  writes B and residual rank.
// ---------------------------------------------------------------------------
__device__ __forceinline__ void select_bin(const unsigned* __restrict__ hist,
                                           unsigned* __restrict__ part,
                                           unsigned kr,
                                           volatile unsigned* sh_bin,
                                           volatile unsigned* sh_kr) {
    int t = threadIdx.x;
    unsigned s = 0;
#pragma unroll
    for (int i = 0; i < 8; ++i) s += hist[t * 8 + i];
    part[t] = s;
    __syncthreads();

    if (t < 32) {
        unsigned c = 0;
#pragma unroll
        for (int i = 0; i < 8; ++i) c += part[t * 8 + i];
        unsigned v = c;
#pragma unroll
        for (int off = 1; off < 32; off <<= 1) {
            unsigned u = __shfl_down_sync(0xffffffffu, v, off);
            if (t + off < 32) v += u;
        }
        unsigned ab = __shfl_down_sync(0xffffffffu, v, 1);
        if (t == 31) ab = 0;
        unsigned m = __ballot_sync(0xffffffffu, v >= kr);
        int L = 31 - __clz(m);
        if (t == L) {
            unsigned cum = ab;
            int bin = 0; unsigned krn = 1;
            for (int g = 7; g >= 0; --g) {
                int gi = L * 8 + g;
                unsigned pg = part[gi];
                if (cum + pg >= kr) {
                    for (int b = 7; b >= 0; --b) {
                        int bi = gi * 8 + b;
                        unsigned hb = hist[bi];
                        if (cum + hb >= kr) { bin = bi; krn = kr - cum; break; }
                        cum += hb;
                    }
                    break;
                }
                cum += pg;
            }
            *sh_bin = (unsigned)bin;
            *sh_kr  = krn;
        }
    }
    __syncthreads();
}

// ---------------------------------------------------------------------------
// Kernel 2: one CTA per row.
//  - load row, keep ORIGINAL values + monotonic keys of boosted values in smem
//  - coarse 64-bin select via warp-ballot bit-slice counting (no atomics)
//  - fine select: 11 + 11 + 4 bit radix passes, atomics only on candidates
//  - output pass: threshold, write original values, positivity bitmask
// ---------------------------------------------------------------------------
__global__ __launch_bounds__(256)
void topk_kernel(const float* __restrict__ in, float* __restrict__ out) {
    extern __shared__ unsigned smem[];
    unsigned* keys  = smem;                         // 8192 words
    float*    vals  = (float*)(smem + 8192);        // 8192 words
    unsigned* hist  = smem + 16384;                 // 2048 words
    unsigned* part  = smem + 16384 + 2048;          // 256 words
    unsigned* whist = hist;                         // alias: 512 words, used pre-pass2
    __shared__ unsigned sh_bin, sh_kr;

    const int t = threadIdx.x;
    const int lane = t & 31, w = t >> 5;
    const int row = blockIdx.x;

    // ---- load pass: values -> smem, keys -> smem, coarse 64-bin ballot hist
    const float4* __restrict__ rowp =
        reinterpret_cast<const float4*>(in) + (size_t)row * (F_COLS / 4);
    const float4* __restrict__ bp = reinterpret_cast<const float4*>(g_boost);

    unsigned cnt_lo = 0, cnt_hi = 0;   // lane l counts bins l and l+32
#pragma unroll
    for (int it = 0; it < 8; ++it) {
        int i4 = it * 256 + t;
        float4 vv = rowp[i4];
        float4 bb = bp[i4];
        reinterpret_cast<float4*>(vals)[i4] = vv;
        float f0 = vv.x * bb.x, f1 = vv.y * bb.y, f2 = vv.z * bb.z, f3 = vv.w * bb.w;
        unsigned u0 = __float_as_uint(f0), u1 = __float_as_uint(f1);
        unsigned u2 = __float_as_uint(f2), u3 = __float_as_uint(f3);
        unsigned k0 = (u0 & 0x80000000u) ? ~u0 : (u0 | 0x80000000u);
        unsigned k1 = (u1 & 0x80000000u) ? ~u1 : (u1 | 0x80000000u);
        unsigned k2 = (u2 & 0x80000000u) ? ~u2 : (u2 | 0x80000000u);
        unsigned k3 = (u3 & 0x80000000u) ? ~u3 : (u3 | 0x80000000u);
        reinterpret_cast<uint4*>(keys)[i4] = make_uint4(k0, k1, k2, k3);
        unsigned kk[4] = {k0, k1, k2, k3};
#pragma unroll
        for (int c = 0; c < 4; ++c) {
            unsigned bin = kk[c] >> 26;        // top 6 bits
            unsigned m0 = __ballot_sync(0xffffffffu, bin & 1u);
            unsigned m1 = __ballot_sync(0xffffffffu, bin & 2u);
            unsigned m2 = __ballot_sync(0xffffffffu, bin & 4u);
            unsigned m3 = __ballot_sync(0xffffffffu, bin & 8u);
            unsigned m4 = __ballot_sync(0xffffffffu, bin & 16u);
            unsigned m5 = __ballot_sync(0xffffffffu, bin & 32u);
            unsigned sel = ((lane & 1)  ? m0 : ~m0)
                         & ((lane & 2)  ? m1 : ~m1)
                         & ((lane & 4)  ? m2 : ~m2)
                         & ((lane & 8)  ? m3 : ~m3)
                         & ((lane & 16) ? m4 : ~m4);
            cnt_lo += __popc(sel & ~m5);
            cnt_hi += __popc(sel & m5);
        }
    }
    whist[w * 64 + lane]      = cnt_lo;
    whist[w * 64 + 32 + lane] = cnt_hi;
    __syncthreads();

    // ---- coarse select among 64 bins (warp 0)
    if (t < 32) {
        unsigned lo = 0, hi = 0;
#pragma unroll
        for (int ww = 0; ww < 8; ++ww) {
            lo += whist[ww * 64 + t];
            hi += whist[ww * 64 + 32 + t];
        }
        unsigned slo = lo, shi = hi;     // inclusive suffix sums
#pragma unroll
        for (int off = 1; off < 32; off <<= 1) {
            unsigned a = __shfl_down_sync(0xffffffffu, slo, off);
            unsigned b = __shfl_down_sync(0xffffffffu, shi, off);
            if (t + off < 32) { slo += a; shi += b; }
        }
        unsigned hitot = __shfl_sync(0xffffffffu, shi, 0);
        unsigned slo1 = __shfl_down_sync(0xffffffffu, slo, 1);
        unsigned shi1 = __shfl_down_sync(0xffffffffu, shi, 1);
        if (t == 31) { slo1 = 0; shi1 = 0; }
        unsigned mh = __ballot_sync(0xffffffffu, shi >= K_SEL);
        if (mh) {
            int L = 31 - __clz(mh);
            if (t == L) { sh_bin = (unsigned)(L + 32); sh_kr = K_SEL - shi1; }
        } else {
            unsigned ml = __ballot_sync(0xffffffffu, slo + hitot >= K_SEL);
            int L = 31 - __clz(ml);
            if (t == L) { sh_bin = (unsigned)L; sh_kr = K_SEL - (slo1 + hitot); }
        }
    }
    __syncthreads();
    const unsigned cb = sh_bin;
    const unsigned kr2 = sh_kr;
    __syncthreads();   // whist (aliased with hist) fully consumed before zeroing

    // ---- pass 2: bits 25..15 over candidates matching coarse bin
    for (int i = t; i < 2048; i += 256) hist[i] = 0;
    __syncthreads();
#pragma unroll
    for (int it = 0; it < 8; ++it) {
        uint4 kk = reinterpret_cast<const uint4*>(keys)[it * 256 + t];
        if ((kk.x >> 26) == cb) atomicAdd(&hist[(kk.x >> 15) & 0x7FFu], 1u);
        if ((kk.y >> 26) == cb) atomicAdd(&hist[(kk.y >> 15) & 0x7FFu], 1u);
        if ((kk.z >> 26) == cb) atomicAdd(&hist[(kk.z >> 15) & 0x7FFu], 1u);
        if ((kk.w >> 26) == cb) atomicAdd(&hist[(kk.w >> 15) & 0x7FFu], 1u);
    }
    __syncthreads();
    select_bin(hist, part, kr2, &sh_bin, &sh_kr);
    const unsigned pref17 = (cb << 11) | sh_bin;
    const unsigned kr3 = sh_kr;
    __syncthreads();

    // ---- pass 3: bits 14..4 over candidates matching 17-bit prefix
    for (int i = t; i < 2048; i += 256) hist[i] = 0;
    __syncthreads();
#pragma unroll
    for (int it = 0; it < 8; ++it) {
        uint4 kk = reinterpret_cast<const uint4*>(keys)[it * 256 + t];
        if ((kk.x >> 15) == pref17) atomicAdd(&hist[(kk.x >> 4) & 0x7FFu], 1u);
        if ((kk.y >> 15) == pref17) atomicAdd(&hist[(kk.y >> 4) & 0x7FFu], 1u);
        if ((kk.z >> 15) == pref17) atomicAdd(&hist[(kk.z >> 4) & 0x7FFu], 1u);
        if ((kk.w >> 15) == pref17) atomicAdd(&hist[(kk.w >> 4) & 0x7FFu], 1u);
    }
    __syncthreads();
    select_bin(hist, part, kr3, &sh_bin, &sh_kr);
    const unsigned pref28 = (pref17 << 11) | sh_bin;
    const unsigned kr4 = sh_kr;
    __syncthreads();

    // ---- pass 4: last 4 bits among elements matching 28-bit prefix
    if (t < 16) hist[t] = 0;
    __syncthreads();
#pragma unroll
    for (int it = 0; it < 8; ++it) {
        uint4 kk = reinterpret_cast<const uint4*>(keys)[it * 256 + t];
        if ((kk.x >> 4) == pref28) atomicAdd(&hist[kk.x & 0xFu], 1u);
        if ((kk.y >> 4) == pref28) atomicAdd(&hist[kk.y & 0xFu], 1u);
        if ((kk.z >> 4) == pref28) atomicAdd(&hist[kk.z & 0xFu], 1u);
        if ((kk.w >> 4) == pref28) atomicAdd(&hist[kk.w & 0xFu], 1u);
    }
    __syncthreads();
    if (t < 32) {
        unsigned c = (t < 16) ? hist[t] : 0u;
        unsigned s = c;
#pragma unroll
        for (int off = 1; off < 16; off <<= 1) {
            unsigned a = __shfl_down_sync(0xffffffffu, s, off);
            if (t + off < 16) s += a;
        }
        unsigned m = __ballot_sync(0xffffffffu, (t < 16) && s >= kr4);
        int L = 31 - __clz(m);
        if (t == L) sh_bin = (unsigned)L;
    }
    __syncthreads();
    const unsigned T = (pref28 << 4) | sh_bin;   // k-th largest key

    // ---- output pass: threshold, write ORIGINAL values, positivity bitmask
    float* __restrict__ orow = out + (size_t)row * F_COLS;
#pragma unroll 4
    for (int it = 0; it < 32; ++it) {
        int j = it * 256 + t;
        unsigned key = keys[j];
        bool kept = key >= T;
        float val = kept ? vals[j] : 0.0f;
        orow[j] = val;
        unsigned bal = __ballot_sync(0xffffffffu, val > 0.0f);
        if (lane == 0)
            g_mask[(size_t)(it * 8 + w) * N_ROWS + row] = bal;
    }
}

// ---------------------------------------------------------------------------
// Kernel 3: column counts via ballot bit-transpose, then EMA.
// ---------------------------------------------------------------------------
__global__ __launch_bounds__(256)
void dc_kernel(const float* __restrict__ dc, float* __restrict__ dcout) {
    __shared__ unsigned s[256];
    const int t = threadIdx.x, lane = t & 31, wi = t >> 5;
    const int wc = blockIdx.x;
    const unsigned* __restrict__ mp = g_mask + (size_t)wc * N_ROWS;

    unsigned cnt = 0;
    const int r0 = wi * 1024;
    for (int g = 0; g < 32; ++g) {
        unsigned word = mp[r0 + g * 32 + lane];
#pragma unroll
        for (int i = 0; i < 32; ++i) {
            unsigned bal = __ballot_sync(0xffffffffu, (word >> i) & 1u);
            if (lane == i) cnt += __popc(bal);
        }
    }
    s[t] = cnt;
    __syncthreads();
    if (t < 32) {
        unsigned tot = 0;
#pragma unroll
        for (int i = 0; i < 8; ++i) tot += s[i * 32 + t];
        int col = wc * 32 + t;
        dcout[col] = 0.9f * dc[col] + 0.1f * (float)tot;
    }
}

// ---------------------------------------------------------------------------
extern "C" void kernel_launch(void* const* d_in, const int* in_sizes, int n_in,
                              void* d_out, int out_size) {
    const float* inputs = (const float*)d_in[0];
    const float* dc     = (const float*)d_in[1];
    if (n_in >= 2 && in_sizes[0] < in_sizes[1]) {
        const float* tmp = inputs; inputs = dc; dc = tmp;
    }
    float* out = (float*)d_out;

    boost_kernel<<<(F_COLS + 255) / 256, 256>>>(dc);

    const int smem_bytes = (8192 + 8192 + 2048 + 256) * 4;   // 74752 B
    cudaFuncSetAttribute(topk_kernel,
                         cudaFuncAttributeMaxDynamicSharedMemorySize, smem_bytes);
    topk_kernel<<<N_ROWS, 256, smem_bytes>>>(inputs, out);

    if (out_size >= (int)((size_t)N_ROWS * F_COLS + F_COLS)) {
        float* dcout = out + (size_t)N_ROWS * F_COLS;
        dc_kernel<<<WORDS_PER_ROW, 256>>>(dc, dcout);
    }
}

// round 6
// speedup vs baseline: 1.7175x; 1.7175x over previous
#include <cuda_runtime.h>
#include <cstdint>

#define N_ROWS 8192
#define F_COLS 8192
#define K_SEL  2867u

// Scratch (static __device__ arrays — allocation-free per harness rules)
__device__ __align__(16) float g_boost[F_COLS];
__device__ __align__(16) float g_rboost[F_COLS];
// Bit-interleaved positivity mask: word index wc in [0,256):
//   group = wc>>2, b = wc&3; bit i of word <-> column group*128 + 4*i + b
// stored transposed: g_mask[wc * N_ROWS + row]
__device__ unsigned g_mask[256 * N_ROWS];

// ---------------------------------------------------------------------------
// Kernel 1: boost = exp(BETA*(target - duty_cycle)) and its reciprocal
// ---------------------------------------------------------------------------
__global__ void boost_kernel(const float* __restrict__ dc) {
    int j = blockIdx.x * blockDim.x + threadIdx.x;
    if (j < F_COLS) {
        const float target = 2867.0f / 8192.0f;   // exact dyadic
        float b = expf(1.5f * (target - dc[j]));
        g_boost[j]  = b;
        g_rboost[j] = 1.0f / b;
    }
}

// ---------------------------------------------------------------------------
// Radix-select over a 2048-bin histogram: find bin B with
//   count(bins > B) < kr <= count(bins >= B);  writes B and residual rank.
// ---------------------------------------------------------------------------
__device__ __forceinline__ void select_bin(const unsigned* __restrict__ hist,
                                           unsigned* __restrict__ part,
                                           unsigned kr,
                                           volatile unsigned* sh_bin,
                                           volatile unsigned* sh_kr) {
    int t = threadIdx.x;
    unsigned s = 0;
#pragma unroll
    for (int i = 0; i < 8; ++i) s += hist[t * 8 + i];
    part[t] = s;
    __syncthreads();

    if (t < 32) {
        unsigned c = 0;
#pragma unroll
        for (int i = 0; i < 8; ++i) c += part[t * 8 + i];
        unsigned v = c;
#pragma unroll
        for (int off = 1; off < 32; off <<= 1) {
            unsigned u = __shfl_down_sync(0xffffffffu, v, off);
            if (t + off < 32) v += u;
        }
        unsigned ab = __shfl_down_sync(0xffffffffu, v, 1);
        if (t == 31) ab = 0;
        unsigned m = __ballot_sync(0xffffffffu, v >= kr);
        int L = 31 - __clz(m);
        if (t == L) {
            unsigned cum = ab;
            int bin = 0; unsigned krn = 1;
            for (int g = 7; g >= 0; --g) {
                int gi = L * 8 + g;
                unsigned pg = part[gi];
                if (cum + pg >= kr) {
                    for (int b = 7; b >= 0; --b) {
                        int bi = gi * 8 + b;
                        unsigned hb = hist[bi];
                        if (cum + hb >= kr) { bin = bi; krn = kr - cum; break; }
                        cum += hb;
                    }
                    break;
                }
                cum += pg;
            }
            *sh_bin = (unsigned)bin;
            *sh_kr  = krn;
        }
    }
    __syncthreads();
}

// ---------------------------------------------------------------------------
// Kernel 2: one CTA per row.
//  pass 1 : load row, monotonic keys -> smem, 2048-bin atomic hist (bits 31..21)
//  collect: candidates in threshold bin -> compact list (expected ~200)
//  level 2: 2048-bin hist of LIST by bits 20..10
//  level 3: 1024-bin hist of LIST by bits  9..0   -> exact k-th key T
//  (fallback to full-sweep passes if candidate bin > 1024 elements)
//  output : vectorized threshold write + bit-interleaved positivity mask
// ---------------------------------------------------------------------------
__global__ __launch_bounds__(256)
void topk_kernel(const float* __restrict__ in, float* __restrict__ out) {
    extern __shared__ unsigned smem[];
    unsigned* keys = smem;                  // 8192 words
    unsigned* hist = smem + 8192;           // 2048 words
    unsigned* list = smem + 8192 + 2048;    // 1024 words
    unsigned* part = smem + 8192 + 3072;    // 256 words
    __shared__ unsigned sh_bin, sh_kr, sh_cnt;

    const int t = threadIdx.x;
    const int lane = t & 31, w = t >> 5;
    const int row = blockIdx.x;

    for (int i = t; i < 2048; i += 256) hist[i] = 0;
    __syncthreads();

    // ---- pass 1: read row, form keys, hist top 11 bits
    const float4* __restrict__ rowp =
        reinterpret_cast<const float4*>(in) + (size_t)row * (F_COLS / 4);
    const float4* __restrict__ bp = reinterpret_cast<const float4*>(g_boost);
#pragma unroll
    for (int it = 0; it < 8; ++it) {
        int i4 = it * 256 + t;
        float4 v = rowp[i4];
        float4 b = bp[i4];
        float f0 = v.x * b.x, f1 = v.y * b.y, f2 = v.z * b.z, f3 = v.w * b.w;
        unsigned u0 = __float_as_uint(f0), u1 = __float_as_uint(f1);
        unsigned u2 = __float_as_uint(f2), u3 = __float_as_uint(f3);
        unsigned k0 = (u0 & 0x80000000u) ? ~u0 : (u0 | 0x80000000u);
        unsigned k1 = (u1 & 0x80000000u) ? ~u1 : (u1 | 0x80000000u);
        unsigned k2 = (u2 & 0x80000000u) ? ~u2 : (u2 | 0x80000000u);
        unsigned k3 = (u3 & 0x80000000u) ? ~u3 : (u3 | 0x80000000u);
        reinterpret_cast<uint4*>(keys)[i4] = make_uint4(k0, k1, k2, k3);
        atomicAdd(&hist[k0 >> 21], 1u);
        atomicAdd(&hist[k1 >> 21], 1u);
        atomicAdd(&hist[k2 >> 21], 1u);
        atomicAdd(&hist[k3 >> 21], 1u);
    }
    __syncthreads();

    select_bin(hist, part, K_SEL, &sh_bin, &sh_kr);
    const unsigned B1 = sh_bin;
    const unsigned kr2 = sh_kr;
    const unsigned m = hist[B1];        // candidates in threshold bin

    unsigned pref22, kr3;
    if (m <= 1024u) {
        // ---- collect candidates into compact list
        if (t == 0) sh_cnt = 0;
        __syncthreads();
#pragma unroll
        for (int it = 0; it < 8; ++it) {
            uint4 kk = reinterpret_cast<const uint4*>(keys)[it * 256 + t];
            if ((kk.x >> 21) == B1) list[atomicAdd(&sh_cnt, 1u)] = kk.x;
            if ((kk.y >> 21) == B1) list[atomicAdd(&sh_cnt, 1u)] = kk.y;
            if ((kk.z >> 21) == B1) list[atomicAdd(&sh_cnt, 1u)] = kk.z;
            if ((kk.w >> 21) == B1) list[atomicAdd(&sh_cnt, 1u)] = kk.w;
        }
        __syncthreads();

        // ---- level 2 on list: bits 20..10
        for (int i = t; i < 2048; i += 256) hist[i] = 0;
        __syncthreads();
        for (unsigned i = t; i < m; i += 256)
            atomicAdd(&hist[(list[i] >> 10) & 0x7FFu], 1u);
        __syncthreads();
        select_bin(hist, part, kr2, &sh_bin, &sh_kr);
        pref22 = (B1 << 11) | sh_bin;
        kr3 = sh_kr;

        // ---- level 3 on list: bits 9..0 (1024 bins; upper half stays 0)
        __syncthreads();
        for (int i = t; i < 2048; i += 256) hist[i] = 0;
        __syncthreads();
        for (unsigned i = t; i < m; i += 256) {
            unsigned k = list[i];
            if ((k >> 10) == pref22) atomicAdd(&hist[k & 0x3FFu], 1u);
        }
        __syncthreads();
        select_bin(hist, part, kr3, &sh_bin, &sh_kr);
    } else {
        // ---- fallback: full-sweep radix passes (correct for any input)
        for (int i = t; i < 2048; i += 256) hist[i] = 0;
        __syncthreads();
#pragma unroll
        for (int it = 0; it < 8; ++it) {
            uint4 kk = reinterpret_cast<const uint4*>(keys)[it * 256 + t];
            if ((kk.x >> 21) == B1) atomicAdd(&hist[(kk.x >> 10) & 0x7FFu], 1u);
            if ((kk.y >> 21) == B1) atomicAdd(&hist[(kk.y >> 10) & 0x7FFu], 1u);
            if ((kk.z >> 21) == B1) atomicAdd(&hist[(kk.z >> 10) & 0x7FFu], 1u);
            if ((kk.w >> 21) == B1) atomicAdd(&hist[(kk.w >> 10) & 0x7FFu], 1u);
        }
        __syncthreads();
        select_bin(hist, part, kr2, &sh_bin, &sh_kr);
        pref22 = (B1 << 11) | sh_bin;
        kr3 = sh_kr;

        __syncthreads();
        for (int i = t; i < 2048; i += 256) hist[i] = 0;
        __syncthreads();
#pragma unroll
        for (int it = 0; it < 8; ++it) {
            uint4 kk = reinterpret_cast<const uint4*>(keys)[it * 256 + t];
            if ((kk.x >> 10) == pref22) atomicAdd(&hist[kk.x & 0x3FFu], 1u);
            if ((kk.y >> 10) == pref22) atomicAdd(&hist[kk.y & 0x3FFu], 1u);
            if ((kk.z >> 10) == pref22) atomicAdd(&hist[kk.z & 0x3FFu], 1u);
            if ((kk.w >> 10) == pref22) atomicAdd(&hist[kk.w & 0x3FFu], 1u);
        }
        __syncthreads();
        select_bin(hist, part, kr3, &sh_bin, &sh_kr);
    }
    const unsigned T = (pref22 << 10) | sh_bin;    // k-th largest key

    // ---- output pass (vectorized): threshold, reconstruct, interleaved mask
    float4* __restrict__ orow =
        reinterpret_cast<float4*>(out) + (size_t)row * (F_COLS / 4);
    const float4* __restrict__ rbp = reinterpret_cast<const float4*>(g_rboost);
#pragma unroll
    for (int it = 0; it < 8; ++it) {
        int i4 = it * 256 + t;
        uint4 kk = reinterpret_cast<const uint4*>(keys)[i4];
        float4 rb = rbp[i4];
        bool c0 = kk.x >= T, c1 = kk.y >= T, c2 = kk.z >= T, c3 = kk.w >= T;
        unsigned b0 = (kk.x & 0x80000000u) ? (kk.x & 0x7FFFFFFFu) : ~kk.x;
        unsigned b1 = (kk.y & 0x80000000u) ? (kk.y & 0x7FFFFFFFu) : ~kk.y;
        unsigned b2 = (kk.z & 0x80000000u) ? (kk.z & 0x7FFFFFFFu) : ~kk.z;
        unsigned b3 = (kk.w & 0x80000000u) ? (kk.w & 0x7FFFFFFFu) : ~kk.w;
        float4 o;
        o.x = c0 ? __uint_as_float(b0) * rb.x : 0.0f;
        o.y = c1 ? __uint_as_float(b1) * rb.y : 0.0f;
        o.z = c2 ? __uint_as_float(b2) * rb.z : 0.0f;
        o.w = c3 ? __uint_as_float(b3) * rb.w : 0.0f;
        orow[i4] = o;
        // positivity ballots (bit-interleaved layout)
        unsigned m0 = __ballot_sync(0xffffffffu, c0 && kk.x > 0x80000000u);
        unsigned m1 = __ballot_sync(0xffffffffu, c1 && kk.y > 0x80000000u);
        unsigned m2 = __ballot_sync(0xffffffffu, c2 && kk.z > 0x80000000u);
        unsigned m3 = __ballot_sync(0xffffffffu, c3 && kk.w > 0x80000000u);
        int group = it * 8 + w;          // 128-column group, 0..63
        size_t base = (size_t)(group * 4) * N_ROWS + row;
        if (lane == 0) g_mask[base]              = m0;
        if (lane == 1) g_mask[base + N_ROWS]     = m1;
        if (lane == 2) g_mask[base + 2 * N_ROWS] = m2;
        if (lane == 3) g_mask[base + 3 * N_ROWS] = m3;
    }
}

// ---------------------------------------------------------------------------
// Kernel 3: column counts via ballot bit-transpose, then EMA.
// Block wc owns mask word-column wc; bit i <-> column (wc>>2)*128+4*i+(wc&3).
// ---------------------------------------------------------------------------
__global__ __launch_bounds__(256)
void dc_kernel(const float* __restrict__ dc, float* __restrict__ dcout) {
    __shared__ unsigned s[256];
    const int t = threadIdx.x, lane = t & 31, wi = t >> 5;
    const int wc = blockIdx.x;
    const unsigned* __restrict__ mp = g_mask + (size_t)wc * N_ROWS;

    unsigned cnt = 0;
    const int r0 = wi * 1024;
    for (int g = 0; g < 32; ++g) {
        unsigned word = mp[r0 + g * 32 + lane];
#pragma unroll
        for (int i = 0; i < 32; ++i) {
            unsigned bal = __ballot_sync(0xffffffffu, (word >> i) & 1u);
            if (lane == i) cnt += __popc(bal);
        }
    }
    s[t] = cnt;
    __syncthreads();
    if (t < 32) {
        unsigned tot = 0;
#pragma unroll
        for (int i = 0; i < 8; ++i) tot += s[i * 32 + t];
        int col = (wc >> 2) * 128 + 4 * t + (wc & 3);
        dcout[col] = 0.9f * dc[col] + 0.1f * (float)tot;
    }
}

// ---------------------------------------------------------------------------
extern "C" void kernel_launch(void* const* d_in, const int* in_sizes, int n_in,
                              void* d_out, int out_size) {
    const float* inputs = (const float*)d_in[0];
    const float* dc     = (const float*)d_in[1];
    if (n_in >= 2 && in_sizes[0] < in_sizes[1]) {
        const float* tmp = inputs; inputs = dc; dc = tmp;
    }
    float* out = (float*)d_out;

    boost_kernel<<<(F_COLS + 255) / 256, 256>>>(dc);

    const int smem_bytes = (8192 + 2048 + 1024 + 256) * 4;   // 46080 B
    topk_kernel<<<N_ROWS, 256, smem_bytes>>>(inputs, out);

    if (out_size >= (int)((size_t)N_ROWS * F_COLS + F_COLS)) {
        float* dcout = out + (size_t)N_ROWS * F_COLS;
        dc_kernel<<<256, 256>>>(dc, dcout);
    }
}